// round 13
// baseline (speedup 1.0000x reference)
#include <cuda_runtime.h>
#include <math.h>

// Problem constants
#define Bq  4
#define Lq  2048
#define Dq  1024
#define Hq  16
#define HDq 64

typedef unsigned long long u64;

// Scratch (allocation-free rule: __device__ globals)
__device__ float g_q [(size_t)Bq * Lq * Dq];
__device__ float g_k [(size_t)Bq * Lq * Dq];
__device__ float g_v [(size_t)Bq * Lq * Dq];
__device__ float g_oh[(size_t)Bq * Lq * Dq];
// Fallback attention scratch in case d_out only holds `out`
__device__ float g_attn[(size_t)Bq * Hq * Lq * Lq];

// ---------------------------------------------------------------------------
// Packed f32x2 helpers
// ---------------------------------------------------------------------------
__device__ __forceinline__ void fma2(u64& d, u64 a, u64 b) {
    asm("fma.rn.f32x2 %0, %1, %2, %0;" : "+l"(d) : "l"(a), "l"(b));
}
__device__ __forceinline__ void mul2(u64& d, u64 a, u64 b) {
    asm("mul.rn.f32x2 %0, %1, %2;" : "=l"(d) : "l"(a), "l"(b));
}
__device__ __forceinline__ void add2(u64& d, u64 a, u64 b) {
    asm("add.rn.f32x2 %0, %1, %2;" : "=l"(d) : "l"(a), "l"(b));
}
__device__ __forceinline__ u64 dup2(float x) {
    u64 r;
    asm("mov.b64 %0, {%1, %1};" : "=l"(r) : "f"(x));
    return r;
}

// ---------------------------------------------------------------------------
// NT GEMM: C[m,n] = alpha * sum_k A[m,k]*B[n,k] (+bias[n])
// 128x128 tile, BK=8, 256 threads, 8x8 outputs as packed f32x2 accumulators.
// Double-buffered smem + register prefetch. Batched over blockIdx.z.
// ---------------------------------------------------------------------------
__global__ __launch_bounds__(256)
void gemm_nt(const float* __restrict__ A, const float* __restrict__ B,
             float* __restrict__ C,
             int K, int lda, int ldb, int ldc,
             long long sA1, long long sA2,
             long long sB1, long long sB2,
             long long sC1, long long sC2, int Hdiv,
             float alpha, const float* __restrict__ bias)
{
    int z  = blockIdx.z;
    int bq = z / Hdiv, hq = z % Hdiv;
    A += (long long)bq * sA1 + (long long)hq * sA2;
    B += (long long)bq * sB1 + (long long)hq * sB2;
    C += (long long)bq * sC1 + (long long)hq * sC2;

    const int bm = blockIdx.y * 128;
    const int bn = blockIdx.x * 128;

    __shared__ float As[2][8][128];
    __shared__ float Bs[2][8][128];

    const int tid = threadIdx.x;
    const int tx  = tid & 15;
    const int ty  = tid >> 4;
    const int lr  = tid >> 1;
    const int lk  = (tid & 1) << 2;

    const float* Ap = A + (long long)(bm + lr) * lda + lk;
    const float* Bp = B + (long long)(bn + lr) * ldb + lk;

    u64 acc[8][4];
#pragma unroll
    for (int i = 0; i < 8; i++)
#pragma unroll
        for (int j = 0; j < 4; j++) acc[i][j] = 0ull;

    float4 a4 = *(const float4*)(Ap);
    float4 b4 = *(const float4*)(Bp);
    As[0][lk + 0][lr] = a4.x; As[0][lk + 1][lr] = a4.y;
    As[0][lk + 2][lr] = a4.z; As[0][lk + 3][lr] = a4.w;
    Bs[0][lk + 0][lr] = b4.x; Bs[0][lk + 1][lr] = b4.y;
    Bs[0][lk + 2][lr] = b4.z; Bs[0][lk + 3][lr] = b4.w;
    __syncthreads();

    int p = 0;
    for (int k0 = 0; k0 < K; k0 += 8) {
        const bool nxt = (k0 + 8) < K;
        if (nxt) {
            a4 = *(const float4*)(Ap + k0 + 8);
            b4 = *(const float4*)(Bp + k0 + 8);
        }
#pragma unroll
        for (int kk = 0; kk < 8; kk++) {
            float ar[8];
            *(float4*)(ar)     = *(const float4*)(&As[p][kk][ty * 4]);
            *(float4*)(ar + 4) = *(const float4*)(&As[p][kk][ty * 4 + 64]);
            ulonglong2 bl0 = *(const ulonglong2*)(&Bs[p][kk][tx * 4]);
            ulonglong2 bl1 = *(const ulonglong2*)(&Bs[p][kk][tx * 4 + 64]);
            u64 bb[4] = { bl0.x, bl0.y, bl1.x, bl1.y };
#pragma unroll
            for (int i = 0; i < 8; i++) {
                u64 ad = dup2(ar[i]);
#pragma unroll
                for (int j = 0; j < 4; j++) fma2(acc[i][j], ad, bb[j]);
            }
        }
        if (nxt) {
            p ^= 1;
            As[p][lk + 0][lr] = a4.x; As[p][lk + 1][lr] = a4.y;
            As[p][lk + 2][lr] = a4.z; As[p][lk + 3][lr] = a4.w;
            Bs[p][lk + 0][lr] = b4.x; Bs[p][lk + 1][lr] = b4.y;
            Bs[p][lk + 2][lr] = b4.z; Bs[p][lk + 3][lr] = b4.w;
            __syncthreads();
        }
    }

    u64 alpha2 = dup2(alpha);
#pragma unroll
    for (int ih = 0; ih < 2; ih++) {
#pragma unroll
        for (int i = 0; i < 4; i++) {
            int r = bm + ty * 4 + i + ih * 64;
#pragma unroll
            for (int jh = 0; jh < 2; jh++) {
                int c = bn + tx * 4 + jh * 64;
                u64 v0 = acc[ih * 4 + i][jh * 2 + 0];
                u64 v1 = acc[ih * 4 + i][jh * 2 + 1];
                mul2(v0, v0, alpha2);
                mul2(v1, v1, alpha2);
                if (bias) {
                    ulonglong2 bb = *(const ulonglong2*)(&bias[c]);
                    add2(v0, v0, bb.x);
                    add2(v1, v1, bb.y);
                }
                ulonglong2 ov; ov.x = v0; ov.y = v1;
                *(ulonglong2*)(C + (long long)r * ldc + c) = ov;
            }
        }
    }
}

// ---------------------------------------------------------------------------
// Fused softmax + AV.
// Block = 128 rows of one (b,h) head. 256 threads.
// Phase 1: row maxes over the 2048-wide energy rows.
// Phase 2: per 32-col chunk: p = exp(e - max); write p (unnormalized) to attn;
//          stage P-chunk (k-major) + V-chunk in smem; accumulate O += P@V.
// Phase 3: rowsum -> 1/s; scale O and write out_head; rescale attn in place.
// ---------------------------------------------------------------------------
__global__ __launch_bounds__(256)
void fused_sm_av(float* __restrict__ E,        // attn buffer [B*H][L][L]
                 const float* __restrict__ V,  // [B][L][D]
                 float* __restrict__ C)        // out_head [B][L][D]
{
    const int z  = blockIdx.y;
    const int bq = z / Hq, hq = z % Hq;
    const int bm = blockIdx.x * 128;

    float* Eb = E + (long long)z * Lq * Lq + (long long)bm * Lq;
    const float* Vb = V + (long long)bq * Lq * Dq + hq * HDq;
    float*       Cb = C + (long long)bq * Lq * Dq + hq * HDq;

    __shared__ float Ps[32][132];     // [kk][m], padded stride
    __shared__ float Vs[32][64];      // [kk][n]
    __shared__ float halfred[256];
    __shared__ float rowmax[128];
    __shared__ float rowsuminv[128];

    const int tid = threadIdx.x;
    const int row = tid >> 1;         // 0..127 (E row handled by this thread)
    const int sub = tid & 1;          // which interleaved half of the row
    const int tx  = tid & 15;         // AV: output col group (4 cols)
    const int ty  = tid >> 4;         // AV: output row group

    float* erow = Eb + (long long)row * Lq;

    // ---- Phase 1: row max ----
    float m = -3.402823466e+38f;
#pragma unroll 4
    for (int jj = 0; jj < 256; jj++) {
        float4 x = *(const float4*)(erow + sub * 4 + 8 * jj);
        m = fmaxf(m, fmaxf(fmaxf(x.x, x.y), fmaxf(x.z, x.w)));
    }
    halfred[tid] = m;
    __syncthreads();
    if (tid < 128)
        rowmax[tid] = fmaxf(halfred[2 * tid], halfred[2 * tid + 1]);
    __syncthreads();
    const float rmax = rowmax[row];

    // ---- Phase 2: exp + write unnormalized + AV accumulate ----
    const int vrow = tid >> 3;            // 0..31 (V chunk row)
    const int vc   = (tid & 7) * 4;       // V col base (float4 granularity)

    u64 acc[8][2];
#pragma unroll
    for (int i = 0; i < 8; i++) { acc[i][0] = 0ull; acc[i][1] = 0ull; }

    float psum = 0.f;

    for (int k0 = 0; k0 < Lq; k0 += 32) {
        // load E chunk (4 float4 per thread) + V chunk (2 float4 per thread)
        float4 ex[4];
#pragma unroll
        for (int jj = 0; jj < 4; jj++)
            ex[jj] = *(const float4*)(erow + k0 + sub * 4 + 8 * jj);
        float4 vv0 = *(const float4*)(Vb + (long long)(k0 + vrow) * Dq + vc);
        float4 vv1 = *(const float4*)(Vb + (long long)(k0 + vrow) * Dq + vc + 32);

        // exp
#pragma unroll
        for (int jj = 0; jj < 4; jj++) {
            ex[jj].x = expf(ex[jj].x - rmax);
            ex[jj].y = expf(ex[jj].y - rmax);
            ex[jj].z = expf(ex[jj].z - rmax);
            ex[jj].w = expf(ex[jj].w - rmax);
            psum += ex[jj].x + ex[jj].y + ex[jj].z + ex[jj].w;
        }

        __syncthreads();   // previous chunk's AV reads done

        // stage P (k-major) and V; write unnormalized p to global
#pragma unroll
        for (int jj = 0; jj < 4; jj++) {
            int kk = sub * 4 + 8 * jj;
            Ps[kk + 0][row] = ex[jj].x;
            Ps[kk + 1][row] = ex[jj].y;
            Ps[kk + 2][row] = ex[jj].z;
            Ps[kk + 3][row] = ex[jj].w;
            *(float4*)(erow + k0 + kk) = ex[jj];
        }
        *(float4*)(&Vs[vrow][vc])      = vv0;
        *(float4*)(&Vs[vrow][vc + 32]) = vv1;

        __syncthreads();

        // AV micro-GEMM: O[128x64] += P[128x32] @ V[32x64]
#pragma unroll
        for (int kk = 0; kk < 32; kk++) {
            float ar[8];
            *(float4*)(ar)     = *(const float4*)(&Ps[kk][ty * 4]);
            *(float4*)(ar + 4) = *(const float4*)(&Ps[kk][ty * 4 + 64]);
            ulonglong2 bb = *(const ulonglong2*)(&Vs[kk][tx * 4]);
#pragma unroll
            for (int i = 0; i < 8; i++) {
                u64 ad = dup2(ar[i]);
                fma2(acc[i][0], ad, bb.x);
                fma2(acc[i][1], ad, bb.y);
            }
        }
    }

    // ---- Phase 3: sums, scale O, normalize attn ----
    __syncthreads();
    halfred[tid] = psum;
    __syncthreads();
    if (tid < 128)
        rowsuminv[tid] = 1.0f / (halfred[2 * tid] + halfred[2 * tid + 1]);
    __syncthreads();

    // scale O and write out_head
#pragma unroll
    for (int ih = 0; ih < 2; ih++) {
#pragma unroll
        for (int i = 0; i < 4; i++) {
            int r = ty * 4 + i + ih * 64;
            u64 inv2 = dup2(rowsuminv[r]);
            u64 v0 = acc[ih * 4 + i][0];
            u64 v1 = acc[ih * 4 + i][1];
            mul2(v0, v0, inv2);
            mul2(v1, v1, inv2);
            ulonglong2 ov; ov.x = v0; ov.y = v1;
            *(ulonglong2*)(&Cb[(long long)(bm + r) * Dq + tx * 4]) = ov;
        }
    }

    // normalize attention rows in place (re-read own writes; L2/L1 hot)
    const float rinv = rowsuminv[row];
#pragma unroll 4
    for (int jj = 0; jj < 256; jj++) {
        float* ptr = erow + sub * 4 + 8 * jj;
        float4 x = *(const float4*)(ptr);
        x.x *= rinv; x.y *= rinv; x.z *= rinv; x.w *= rinv;
        *(float4*)(ptr) = x;
    }
}

// ---------------------------------------------------------------------------
// Launch
// ---------------------------------------------------------------------------
extern "C" void kernel_launch(void* const* d_in, const int* in_sizes, int n_in,
                              void* d_out, int out_size)
{
    const float* query = (const float*)d_in[0];
    const float* key   = (const float*)d_in[1];
    const float* value = (const float*)d_in[2];
    const float* Wq    = (const float*)d_in[3];
    const float* Wk    = (const float*)d_in[4];
    const float* Wv    = (const float*)d_in[5];
    const float* Wo    = (const float*)d_in[6];
    const float* bo    = (const float*)d_in[7];

    float* out = (float*)d_out;

    const long long BLD  = (long long)Bq * Lq * Dq;
    const long long BHLL = (long long)Bq * Hq * Lq * Lq;

    float *pq, *pk, *pv, *poh, *pattn_scratch;
    cudaGetSymbolAddress((void**)&pq,  g_q);
    cudaGetSymbolAddress((void**)&pk,  g_k);
    cudaGetSymbolAddress((void**)&pv,  g_v);
    cudaGetSymbolAddress((void**)&poh, g_oh);
    cudaGetSymbolAddress((void**)&pattn_scratch, g_attn);

    float* attn = ((long long)out_size >= BLD + BHLL) ? (out + BLD)
                                                      : pattn_scratch;

    dim3 blk(256);

    // 1) QKV projections
    {
        dim3 grd(Dq / 128, (Bq * Lq) / 128, 1);
        gemm_nt<<<grd, blk>>>(query, Wq, pq, Dq, Dq, Dq, Dq,
                              0, 0, 0, 0, 0, 0, 1, 1.0f, (const float*)0);
        gemm_nt<<<grd, blk>>>(key,   Wk, pk, Dq, Dq, Dq, Dq,
                              0, 0, 0, 0, 0, 0, 1, 1.0f, (const float*)0);
        gemm_nt<<<grd, blk>>>(value, Wv, pv, Dq, Dq, Dq, Dq,
                              0, 0, 0, 0, 0, 0, 1, 1.0f, (const float*)0);
    }

    // 2) Scores: per (b,h): S = (1/8) * Q_bh @ K_bh^T
    {
        dim3 grd(Lq / 128, Lq / 128, Bq * Hq);
        gemm_nt<<<grd, blk>>>(pq, pk, attn, HDq, Dq, Dq, Lq,
                              (long long)Lq * Dq, (long long)HDq,
                              (long long)Lq * Dq, (long long)HDq,
                              (long long)Hq * Lq * Lq, (long long)Lq * Lq,
                              Hq, 0.125f, (const float*)0);
    }

    // 3+4) Fused softmax + AV
    {
        dim3 grd(Lq / 128, Bq * Hq);
        fused_sm_av<<<grd, blk>>>(attn, pv, poh);
    }

    // 5) Output projection: out = out_head @ Wo^T + bo
    {
        dim3 grd(Dq / 128, (Bq * Lq) / 128, 1);
        gemm_nt<<<grd, blk>>>(poh, Wo, out, Dq, Dq, Dq, Dq,
                              0, 0, 0, 0, 0, 0, 1, 1.0f, bo);
    }
}